// round 1
// baseline (speedup 1.0000x reference)
#include <cuda_runtime.h>
#include <math.h>

#define EMBED 512
#define HEADS 8
#define HD 64
#define BB 4
#define SS 2048
#define MROWS (BB * SS) /* 8192 */

// Scratch (allocation-free per harness rules): Q/K/V/context projections + attn fallback.
__device__ float g_q[(size_t)MROWS * EMBED];
__device__ float g_k[(size_t)MROWS * EMBED];
__device__ float g_v[(size_t)MROWS * EMBED];
__device__ float g_ctx[(size_t)MROWS * EMBED];
__device__ float g_attn[(size_t)BB * HEADS * SS * SS];

// ---------------------------------------------------------------------------
// Generic C[M,N] = A[M,K] @ W[K,N] + bias.  64x64 tile, TK=16, 4x4 per thread.
// ---------------------------------------------------------------------------
__global__ __launch_bounds__(256) void gemm_bias_kernel(
    const float* __restrict__ A, const float* __restrict__ W,
    const float* __restrict__ bias, float* __restrict__ C,
    int M, int N, int K)
{
    __shared__ float As[16][64];
    __shared__ float Ws[16][64];
    const int tid = threadIdx.x;
    const int tx = tid & 15, ty = tid >> 4;
    const int row0 = blockIdx.y * 64, col0 = blockIdx.x * 64;

    const int ra = tid >> 2;          // 0..63  (A tile row)
    const int ka = (tid & 3) << 2;    // 0,4,8,12 (A tile k)
    const int kw = tid >> 4;          // 0..15  (W tile k)
    const int cw = (tid & 15) << 2;   // 0..60  (W tile col)

    float acc[4][4] = {};

    for (int t = 0; t < K; t += 16) {
        float4 av = *reinterpret_cast<const float4*>(&A[(size_t)(row0 + ra) * K + t + ka]);
        As[ka + 0][ra] = av.x; As[ka + 1][ra] = av.y;
        As[ka + 2][ra] = av.z; As[ka + 3][ra] = av.w;
        float4 wv = *reinterpret_cast<const float4*>(&W[(size_t)(t + kw) * N + col0 + cw]);
        *reinterpret_cast<float4*>(&Ws[kw][cw]) = wv;
        __syncthreads();
        #pragma unroll
        for (int kk = 0; kk < 16; kk++) {
            float4 a = *reinterpret_cast<const float4*>(&As[kk][ty * 4]);
            float4 w = *reinterpret_cast<const float4*>(&Ws[kk][tx * 4]);
            float ar[4] = {a.x, a.y, a.z, a.w};
            float wr[4] = {w.x, w.y, w.z, w.w};
            #pragma unroll
            for (int i = 0; i < 4; i++)
                #pragma unroll
                for (int j = 0; j < 4; j++)
                    acc[i][j] += ar[i] * wr[j];
        }
        __syncthreads();
    }

    #pragma unroll
    for (int i = 0; i < 4; i++) {
        int r = row0 + ty * 4 + i;
        #pragma unroll
        for (int j = 0; j < 4; j++) {
            int c = col0 + tx * 4 + j;
            C[(size_t)r * N + c] = acc[i][j] + bias[c];
        }
    }
}

// ---------------------------------------------------------------------------
// Scores: S[b,h,q,k] = (Qh[q,:] . Kh[k,:]) * 1/sqrt(64).   Per-(b,h) 2048x2048x64.
// ---------------------------------------------------------------------------
__global__ __launch_bounds__(256) void scores_kernel(
    const float* __restrict__ Q, const float* __restrict__ Kf, float* __restrict__ attn)
{
    const int bh = blockIdx.z;
    const int b = bh >> 3, h = bh & 7;
    const float* Qh = Q + (size_t)b * SS * EMBED + h * HD;
    const float* Kh = Kf + (size_t)b * SS * EMBED + h * HD;
    float* Sh = attn + (size_t)bh * SS * SS;
    const int row0 = blockIdx.y * 64, col0 = blockIdx.x * 64;
    const int tid = threadIdx.x;
    const int tx = tid & 15, ty = tid >> 4;

    __shared__ float Qs[16][64];
    __shared__ float Ks[16][64];
    const int r = tid >> 2;
    const int kq = (tid & 3) << 2;

    float acc[4][4] = {};

    for (int t = 0; t < HD; t += 16) {
        float4 qv = *reinterpret_cast<const float4*>(&Qh[(size_t)(row0 + r) * EMBED + t + kq]);
        Qs[kq + 0][r] = qv.x; Qs[kq + 1][r] = qv.y;
        Qs[kq + 2][r] = qv.z; Qs[kq + 3][r] = qv.w;
        float4 kv = *reinterpret_cast<const float4*>(&Kh[(size_t)(col0 + r) * EMBED + t + kq]);
        Ks[kq + 0][r] = kv.x; Ks[kq + 1][r] = kv.y;
        Ks[kq + 2][r] = kv.z; Ks[kq + 3][r] = kv.w;
        __syncthreads();
        #pragma unroll
        for (int kk = 0; kk < 16; kk++) {
            float4 a = *reinterpret_cast<const float4*>(&Qs[kk][ty * 4]);
            float4 w = *reinterpret_cast<const float4*>(&Ks[kk][tx * 4]);
            float ar[4] = {a.x, a.y, a.z, a.w};
            float wr[4] = {w.x, w.y, w.z, w.w};
            #pragma unroll
            for (int i = 0; i < 4; i++)
                #pragma unroll
                for (int j = 0; j < 4; j++)
                    acc[i][j] += ar[i] * wr[j];
        }
        __syncthreads();
    }

    const float scale = 0.125f; // 1/sqrt(64)
    #pragma unroll
    for (int i = 0; i < 4; i++) {
        int q = row0 + ty * 4 + i;
        #pragma unroll
        for (int j = 0; j < 4; j++) {
            int c = col0 + tx * 4 + j;
            Sh[(size_t)q * SS + c] = acc[i][j] * scale;
        }
    }
}

// ---------------------------------------------------------------------------
// Row softmax in place over rows of length 2048. One block (256 thr) per row.
// ---------------------------------------------------------------------------
__global__ __launch_bounds__(256) void softmax_kernel(float* __restrict__ attn)
{
    float* p = attn + (size_t)blockIdx.x * SS;
    const int tid = threadIdx.x;
    const int w = tid >> 5, l = tid & 31;
    __shared__ float smax[8];
    __shared__ float ssum[8];

    float v[8];
    #pragma unroll
    for (int j = 0; j < 8; j++) v[j] = p[tid + j * 256];

    float m = v[0];
    #pragma unroll
    for (int j = 1; j < 8; j++) m = fmaxf(m, v[j]);
    #pragma unroll
    for (int o = 16; o > 0; o >>= 1) m = fmaxf(m, __shfl_xor_sync(0xffffffffu, m, o));
    if (l == 0) smax[w] = m;
    __syncthreads();
    float bm = smax[0];
    #pragma unroll
    for (int i = 1; i < 8; i++) bm = fmaxf(bm, smax[i]);

    float s = 0.f;
    #pragma unroll
    for (int j = 0; j < 8; j++) { v[j] = __expf(v[j] - bm); s += v[j]; }
    #pragma unroll
    for (int o = 16; o > 0; o >>= 1) s += __shfl_xor_sync(0xffffffffu, s, o);
    if (l == 0) ssum[w] = s;
    __syncthreads();
    float bs = 0.f;
    #pragma unroll
    for (int i = 0; i < 8; i++) bs += ssum[i];

    const float inv = 1.0f / bs;
    #pragma unroll
    for (int j = 0; j < 8; j++) p[tid + j * 256] = v[j] * inv;
}

// ---------------------------------------------------------------------------
// Context: ctx[b, q, h*64+d] = sum_k attn[b,h,q,k] * Vh[k, d].  2048x64x2048 per bh.
// ---------------------------------------------------------------------------
__global__ __launch_bounds__(256) void context_kernel(
    const float* __restrict__ attn, const float* __restrict__ V, float* __restrict__ ctx)
{
    const int bh = blockIdx.z;
    const int b = bh >> 3, h = bh & 7;
    const float* Ah = attn + (size_t)bh * SS * SS;
    const float* Vh = V + (size_t)b * SS * EMBED + h * HD;
    const int row0 = blockIdx.y * 64;
    const int tid = threadIdx.x;
    const int tx = tid & 15, ty = tid >> 4;

    __shared__ float Ats[16][64];
    __shared__ float Vs[16][64];
    const int ra = tid >> 2;
    const int k4 = (tid & 3) << 2;
    const int kw = tid >> 4;
    const int cw = (tid & 15) << 2;

    float acc[4][4] = {};

    for (int t = 0; t < SS; t += 16) {
        float4 av = *reinterpret_cast<const float4*>(&Ah[(size_t)(row0 + ra) * SS + t + k4]);
        Ats[k4 + 0][ra] = av.x; Ats[k4 + 1][ra] = av.y;
        Ats[k4 + 2][ra] = av.z; Ats[k4 + 3][ra] = av.w;
        float4 vv = *reinterpret_cast<const float4*>(&Vh[(size_t)(t + kw) * EMBED + cw]);
        *reinterpret_cast<float4*>(&Vs[kw][cw]) = vv;
        __syncthreads();
        #pragma unroll
        for (int kk = 0; kk < 16; kk++) {
            float4 a = *reinterpret_cast<const float4*>(&Ats[kk][ty * 4]);
            float4 w = *reinterpret_cast<const float4*>(&Vs[kk][tx * 4]);
            float ar[4] = {a.x, a.y, a.z, a.w};
            float wr[4] = {w.x, w.y, w.z, w.w};
            #pragma unroll
            for (int i = 0; i < 4; i++)
                #pragma unroll
                for (int j = 0; j < 4; j++)
                    acc[i][j] += ar[i] * wr[j];
        }
        __syncthreads();
    }

    #pragma unroll
    for (int i = 0; i < 4; i++) {
        int q = row0 + ty * 4 + i;
        #pragma unroll
        for (int j = 0; j < 4; j++) {
            ctx[(size_t)(b * SS + q) * EMBED + h * HD + tx * 4 + j] = acc[i][j];
        }
    }
}

// ---------------------------------------------------------------------------
extern "C" void kernel_launch(void* const* d_in, const int* in_sizes, int n_in,
                              void* d_out, int out_size)
{
    const float* query = (const float*)d_in[0];
    const float* key   = (const float*)d_in[1];
    const float* value = (const float*)d_in[2];
    const float* Wq = (const float*)d_in[3];
    const float* bq = (const float*)d_in[4];
    const float* Wk = (const float*)d_in[5];
    const float* bk = (const float*)d_in[6];
    const float* Wv = (const float*)d_in[7];
    const float* bv = (const float*)d_in[8];
    const float* Wo = (const float*)d_in[9];
    const float* bo = (const float*)d_in[10];
    float* out = (float*)d_out;

    const size_t out_elems  = (size_t)MROWS * EMBED;           // 4,194,304
    const size_t attn_elems = (size_t)BB * HEADS * SS * SS;    // 134,217,728

    float *pq, *pk, *pv, *pctx, *pattn;
    cudaGetSymbolAddress((void**)&pq,    g_q);
    cudaGetSymbolAddress((void**)&pk,    g_k);
    cudaGetSymbolAddress((void**)&pv,    g_v);
    cudaGetSymbolAddress((void**)&pctx,  g_ctx);
    cudaGetSymbolAddress((void**)&pattn, g_attn);

    // If harness exposes the (output, attn) tuple, attn lives in d_out after output.
    float* attn = ((size_t)out_size >= out_elems + attn_elems) ? (out + out_elems) : pattn;

    dim3 gB(EMBED / 64, MROWS / 64);          // (8, 128)
    gemm_bias_kernel<<<gB, 256>>>(query, Wq, bq, pq, MROWS, EMBED, EMBED);
    gemm_bias_kernel<<<gB, 256>>>(key,   Wk, bk, pk, MROWS, EMBED, EMBED);
    gemm_bias_kernel<<<gB, 256>>>(value, Wv, bv, pv, MROWS, EMBED, EMBED);

    dim3 gS(SS / 64, SS / 64, BB * HEADS);    // (32, 32, 32)
    scores_kernel<<<gS, 256>>>(pq, pk, attn);

    softmax_kernel<<<BB * HEADS * SS, 256>>>(attn);

    dim3 gC(1, SS / 64, BB * HEADS);          // (1, 32, 32)
    context_kernel<<<gC, 256>>>(attn, pv, pctx);

    gemm_bias_kernel<<<gB, 256>>>(pctx, Wo, bo, out, MROWS, EMBED, EMBED);
}

// round 3
// speedup vs baseline: 1.4712x; 1.4712x over previous
#include <cuda_runtime.h>
#include <cuda_bf16.h>
#include <stdint.h>
#include <math.h>

#define EMBED 512
#define HEADS 8
#define HD 64
#define BB 4
#define SS 2048
#define MROWS (BB * SS) /* 8192 */
#define NBH (BB * HEADS) /* 32 */

// ------------------------- scratch (no allocs allowed) ----------------------
__device__ float g_q[(size_t)MROWS * EMBED];
__device__ float g_k[(size_t)MROWS * EMBED];
__device__ float g_v[(size_t)MROWS * EMBED];
__device__ float g_ctx[(size_t)MROWS * EMBED];
__device__ float g_attn[(size_t)NBH * SS * SS];
__device__ __nv_bfloat16 g_qh[(size_t)MROWS * EMBED];
__device__ __nv_bfloat16 g_ql[(size_t)MROWS * EMBED];
__device__ __nv_bfloat16 g_kh[(size_t)MROWS * EMBED];
__device__ __nv_bfloat16 g_kl[(size_t)MROWS * EMBED];
__device__ __nv_bfloat16 g_vth[(size_t)NBH * HD * SS];
__device__ __nv_bfloat16 g_vtl[(size_t)NBH * HD * SS];

// ------------------------- helpers -----------------------------------------
__device__ __forceinline__ uint32_t smem_u32(const void* p) {
    uint32_t a;
    asm("{ .reg .u64 t; cvta.to.shared.u64 t, %1; cvt.u32.u64 %0, t; }" : "=r"(a) : "l"(p));
    return a;
}

#define LDSM_X4(r0, r1, r2, r3, a) \
    asm volatile("ldmatrix.sync.aligned.m8n8.x4.shared.b16 {%0,%1,%2,%3}, [%4];" \
                 : "=r"(r0), "=r"(r1), "=r"(r2), "=r"(r3) : "r"(a))

#define MMA_BF16(d, a0, a1, a2, a3, b0, b1) \
    asm volatile("mma.sync.aligned.m16n8k16.row.col.f32.bf16.bf16.f32 " \
                 "{%0,%1,%2,%3}, {%4,%5,%6,%7}, {%8,%9}, {%0,%1,%2,%3};" \
                 : "+f"((d)[0]), "+f"((d)[1]), "+f"((d)[2]), "+f"((d)[3]) \
                 : "r"(a0), "r"(a1), "r"(a2), "r"(a3), "r"(b0), "r"(b1))

__device__ __forceinline__ void split2(float a, float b, uint32_t& h, uint32_t& l) {
    __nv_bfloat16 ha = __float2bfloat16(a), hb = __float2bfloat16(b);
    float la = a - __bfloat162float(ha), lb = b - __bfloat162float(hb);
    __nv_bfloat16 lla = __float2bfloat16(la), llb = __float2bfloat16(lb);
    h = ((uint32_t)__bfloat16_as_ushort(hb) << 16) | (uint32_t)__bfloat16_as_ushort(ha);
    l = ((uint32_t)__bfloat16_as_ushort(llb) << 16) | (uint32_t)__bfloat16_as_ushort(lla);
}

// padded smem stride: 72 bf16 = 144 B (16B-aligned, ldmatrix conflict-free)
#define TSTR 72
#define TSTRB 144
#define TILE128B (128 * TSTRB) /* 18432 */
#define TILE64B  (64 * TSTRB)  /* 9216  */

// ---------------------------------------------------------------------------
// SIMT GEMM (projections + output proj): C[M,N] = A[M,K] @ W[K,N] + bias
// ---------------------------------------------------------------------------
__global__ __launch_bounds__(256) void gemm_bias_kernel(
    const float* __restrict__ A, const float* __restrict__ W,
    const float* __restrict__ bias, float* __restrict__ C,
    int M, int N, int K)
{
    __shared__ float As[16][64];
    __shared__ float Ws[16][64];
    const int tid = threadIdx.x;
    const int tx = tid & 15, ty = tid >> 4;
    const int row0 = blockIdx.y * 64, col0 = blockIdx.x * 64;
    const int ra = tid >> 2;
    const int ka = (tid & 3) << 2;
    const int kw = tid >> 4;
    const int cw = (tid & 15) << 2;
    float acc[4][4] = {};
    for (int t = 0; t < K; t += 16) {
        float4 av = *reinterpret_cast<const float4*>(&A[(size_t)(row0 + ra) * K + t + ka]);
        As[ka + 0][ra] = av.x; As[ka + 1][ra] = av.y;
        As[ka + 2][ra] = av.z; As[ka + 3][ra] = av.w;
        float4 wv = *reinterpret_cast<const float4*>(&W[(size_t)(t + kw) * N + col0 + cw]);
        *reinterpret_cast<float4*>(&Ws[kw][cw]) = wv;
        __syncthreads();
        #pragma unroll
        for (int kk = 0; kk < 16; kk++) {
            float4 a = *reinterpret_cast<const float4*>(&As[kk][ty * 4]);
            float4 w = *reinterpret_cast<const float4*>(&Ws[kk][tx * 4]);
            float ar[4] = {a.x, a.y, a.z, a.w};
            float wr[4] = {w.x, w.y, w.z, w.w};
            #pragma unroll
            for (int i = 0; i < 4; i++)
                #pragma unroll
                for (int j = 0; j < 4; j++)
                    acc[i][j] += ar[i] * wr[j];
        }
        __syncthreads();
    }
    #pragma unroll
    for (int i = 0; i < 4; i++) {
        int r = row0 + ty * 4 + i;
        #pragma unroll
        for (int j = 0; j < 4; j++) {
            int c = col0 + tx * 4 + j;
            C[(size_t)r * N + c] = acc[i][j] + bias[c];
        }
    }
}

// ---------------------------------------------------------------------------
// Elementwise fp32 -> bf16 hi/lo split
// ---------------------------------------------------------------------------
__global__ __launch_bounds__(256) void split_hl_kernel(
    const float4* __restrict__ x, uint2* __restrict__ hi, uint2* __restrict__ lo, int n4)
{
    int i = blockIdx.x * 256 + threadIdx.x;
    if (i >= n4) return;
    float4 f = x[i];
    uint32_t h0, l0, h1, l1;
    split2(f.x, f.y, h0, l0);
    split2(f.z, f.w, h1, l1);
    hi[i] = make_uint2(h0, h1);
    lo[i] = make_uint2(l0, l1);
}

// ---------------------------------------------------------------------------
// V transpose + split: vT[bh][d][s] = split(v[b*S+s][h*64+d])
// ---------------------------------------------------------------------------
__global__ __launch_bounds__(256) void split_vT_kernel(
    const float* __restrict__ v, __nv_bfloat16* __restrict__ vth, __nv_bfloat16* __restrict__ vtl)
{
    __shared__ float tile[32][33];
    const int bh = blockIdx.z, b = bh >> 3, h = bh & 7;
    const int s0 = blockIdx.x * 32, d0 = blockIdx.y * 32;
    const int tx = threadIdx.x, ty = threadIdx.y; // (32, 8)
    #pragma unroll
    for (int j = 0; j < 4; j++) {
        int sl = ty + j * 8;
        tile[sl][tx] = v[(size_t)(b * SS + s0 + sl) * EMBED + h * HD + d0 + tx];
    }
    __syncthreads();
    #pragma unroll
    for (int j = 0; j < 4; j++) {
        int dl = ty + j * 8;
        float f = tile[tx][dl];
        __nv_bfloat16 hb = __float2bfloat16(f);
        __nv_bfloat16 lb = __float2bfloat16(f - __bfloat162float(hb));
        size_t o = ((size_t)bh * HD + d0 + dl) * SS + s0 + tx;
        vth[o] = hb;
        vtl[o] = lb;
    }
}

// ---------------------------------------------------------------------------
// Scores via mma.sync: S = (Q K^T) * 0.125, split-bf16.
// Block 256 thr (8 warps), tile 128x128, warps 2x4 (each 64x32), K = 64.
// smem: Ah(Q hi) | Al | Bh(K hi) | Bl, each 128 rows x 72 bf16.
// ---------------------------------------------------------------------------
#define SC_SMEM (4 * TILE128B) /* 73728 */
__global__ __launch_bounds__(256) void scores_mma(
    const __nv_bfloat16* __restrict__ qh, const __nv_bfloat16* __restrict__ ql,
    const __nv_bfloat16* __restrict__ kh, const __nv_bfloat16* __restrict__ kl,
    float* __restrict__ attn)
{
    extern __shared__ char smem[];
    const uint32_t sb = smem_u32(smem);
    const int tid = threadIdx.x, wid = tid >> 5, lane = tid & 31;
    const int bh = blockIdx.z, b = bh >> 3, h = bh & 7;
    const int row0 = blockIdx.y * 128, col0 = blockIdx.x * 128;
    const uint32_t OA_H = 0, OA_L = TILE128B, OB_H = 2 * TILE128B, OB_L = 3 * TILE128B;

    // load tiles (2 threads per row, 64B each)
    {
        const int lrow = tid >> 1, lhalf = tid & 1;
        size_t qo = (size_t)(b * SS + row0 + lrow) * EMBED + h * HD + lhalf * 32;
        size_t ko = (size_t)(b * SS + col0 + lrow) * EMBED + h * HD + lhalf * 32;
        const uint4* qhp = (const uint4*)(qh + qo);
        const uint4* qlp = (const uint4*)(ql + qo);
        const uint4* khp = (const uint4*)(kh + ko);
        const uint4* klp = (const uint4*)(kl + ko);
        const uint32_t so = (uint32_t)lrow * TSTRB + lhalf * 64;
        #pragma unroll
        for (int i = 0; i < 4; i++) {
            *(uint4*)(smem + OA_H + so + i * 16) = qhp[i];
            *(uint4*)(smem + OA_L + so + i * 16) = qlp[i];
            *(uint4*)(smem + OB_H + so + i * 16) = khp[i];
            *(uint4*)(smem + OB_L + so + i * 16) = klp[i];
        }
    }
    __syncthreads();

    const int wm = wid >> 2, wn = wid & 3; // warp tile 64x32 at (wm*64, wn*32)
    float acc[4][4][4] = {};

    // ldmatrix lane address components
    const uint32_t a_r = lane & 15, a_c = (lane >> 4) * 16;              // A: 16x16
    const uint32_t b_r = (lane & 7) + ((lane >> 4) & 1) * 8;             // B: two 8-row groups
    const uint32_t b_c = ((lane >> 3) & 1) * 16;

    #pragma unroll
    for (int ks = 0; ks < 4; ks++) {
        const uint32_t kb = ks * 32; // 16 bf16 = 32B
        uint32_t a[4][4], bhf[2][4], blf[2][4];
        #pragma unroll
        for (int mf = 0; mf < 4; mf++) {
            uint32_t ad = sb + OA_H + (wm * 64 + mf * 16 + a_r) * TSTRB + kb + a_c;
            LDSM_X4(a[mf][0], a[mf][1], a[mf][2], a[mf][3], ad);
        }
        #pragma unroll
        for (int p = 0; p < 2; p++) {
            uint32_t bd = sb + OB_H + (wn * 32 + p * 16 + b_r) * TSTRB + kb + b_c;
            LDSM_X4(bhf[p][0], bhf[p][1], bhf[p][2], bhf[p][3], bd);
        }
        #pragma unroll
        for (int p = 0; p < 2; p++) {
            uint32_t bd = sb + OB_L + (wn * 32 + p * 16 + b_r) * TSTRB + kb + b_c;
            LDSM_X4(blf[p][0], blf[p][1], blf[p][2], blf[p][3], bd);
        }
        // pass 0: Ah * Bh ; pass 1: Ah * Bl
        #pragma unroll
        for (int mf = 0; mf < 4; mf++)
            #pragma unroll
            for (int nf = 0; nf < 4; nf++) {
                MMA_BF16(acc[mf][nf], a[mf][0], a[mf][1], a[mf][2], a[mf][3],
                         bhf[nf >> 1][(nf & 1) * 2], bhf[nf >> 1][(nf & 1) * 2 + 1]);
                MMA_BF16(acc[mf][nf], a[mf][0], a[mf][1], a[mf][2], a[mf][3],
                         blf[nf >> 1][(nf & 1) * 2], blf[nf >> 1][(nf & 1) * 2 + 1]);
            }
        // pass 2: Al * Bh
        #pragma unroll
        for (int mf = 0; mf < 4; mf++) {
            uint32_t ad = sb + OA_L + (wm * 64 + mf * 16 + a_r) * TSTRB + kb + a_c;
            LDSM_X4(a[mf][0], a[mf][1], a[mf][2], a[mf][3], ad);
        }
        #pragma unroll
        for (int mf = 0; mf < 4; mf++)
            #pragma unroll
            for (int nf = 0; nf < 4; nf++)
                MMA_BF16(acc[mf][nf], a[mf][0], a[mf][1], a[mf][2], a[mf][3],
                         bhf[nf >> 1][(nf & 1) * 2], bhf[nf >> 1][(nf & 1) * 2 + 1]);
    }

    // epilogue: scale + direct STG (float2)
    float* outp = attn + (size_t)bh * SS * SS;
    const int er = lane >> 2, ec = (lane & 3) * 2;
    #pragma unroll
    for (int mf = 0; mf < 4; mf++) {
        int r = row0 + wm * 64 + mf * 16 + er;
        #pragma unroll
        for (int nf = 0; nf < 4; nf++) {
            int c = col0 + wn * 32 + nf * 8 + ec;
            float2 v0 = make_float2(acc[mf][nf][0] * 0.125f, acc[mf][nf][1] * 0.125f);
            float2 v1 = make_float2(acc[mf][nf][2] * 0.125f, acc[mf][nf][3] * 0.125f);
            *(float2*)&outp[(size_t)r * SS + c] = v0;
            *(float2*)&outp[(size_t)(r + 8) * SS + c] = v1;
        }
    }
}

// ---------------------------------------------------------------------------
// Row softmax in place (rows of 2048)
// ---------------------------------------------------------------------------
__global__ __launch_bounds__(256) void softmax_kernel(float* __restrict__ attn)
{
    float* p = attn + (size_t)blockIdx.x * SS;
    const int tid = threadIdx.x;
    const int w = tid >> 5, l = tid & 31;
    __shared__ float smax[8];
    __shared__ float ssum[8];
    float v[8];
    #pragma unroll
    for (int j = 0; j < 8; j++) v[j] = p[tid + j * 256];
    float m = v[0];
    #pragma unroll
    for (int j = 1; j < 8; j++) m = fmaxf(m, v[j]);
    #pragma unroll
    for (int o = 16; o > 0; o >>= 1) m = fmaxf(m, __shfl_xor_sync(0xffffffffu, m, o));
    if (l == 0) smax[w] = m;
    __syncthreads();
    float bm = smax[0];
    #pragma unroll
    for (int i = 1; i < 8; i++) bm = fmaxf(bm, smax[i]);
    float s = 0.f;
    #pragma unroll
    for (int j = 0; j < 8; j++) { v[j] = __expf(v[j] - bm); s += v[j]; }
    #pragma unroll
    for (int o = 16; o > 0; o >>= 1) s += __shfl_xor_sync(0xffffffffu, s, o);
    if (l == 0) ssum[w] = s;
    __syncthreads();
    float bs = 0.f;
    #pragma unroll
    for (int i = 0; i < 8; i++) bs += ssum[i];
    const float inv = 1.0f / bs;
    #pragma unroll
    for (int j = 0; j < 8; j++) p[tid + j * 256] = v[j] * inv;
}

// ---------------------------------------------------------------------------
// Context via mma.sync: ctx[q][h*64+d] = sum_k attn[q][k] vT[d][k]
// Block 256 thr, tile 128(M) x 64(N), warps 4x2 (each 32x32), k in 64-chunks.
// attn fp32 -> bf16 hi/lo conversion in-kernel.
// smem: Ah | Al (128x72) | Bh | Bl (64x72)
// ---------------------------------------------------------------------------
#define CTX_SMEM (2 * TILE128B + 2 * TILE64B) /* 55296 */
__global__ __launch_bounds__(256) void context_mma(
    const float* __restrict__ attn,
    const __nv_bfloat16* __restrict__ vth, const __nv_bfloat16* __restrict__ vtl,
    float* __restrict__ ctx)
{
    extern __shared__ char smem[];
    const uint32_t sb = smem_u32(smem);
    const int tid = threadIdx.x, wid = tid >> 5, lane = tid & 31;
    const int bh = blockIdx.y, b = bh >> 3, h = bh & 7;
    const int row0 = blockIdx.x * 128;
    const uint32_t OA_H = 0, OA_L = TILE128B, OB_H = 2 * TILE128B, OB_L = 2 * TILE128B + TILE64B;

    const float* ap = attn + (size_t)bh * SS * SS;
    const __nv_bfloat16* bhp = vth + (size_t)bh * HD * SS;
    const __nv_bfloat16* blp = vtl + (size_t)bh * HD * SS;

    const int wm = wid >> 1, wn = wid & 1; // warp tile 32x32 at (wm*32, wn*32)
    float acc[2][4][4] = {};

    const uint32_t a_r = lane & 15, a_c = (lane >> 4) * 16;
    const uint32_t b_r = (lane & 7) + ((lane >> 4) & 1) * 8;
    const uint32_t b_c = ((lane >> 3) & 1) * 16;

    const int arow = tid >> 1, ahalf = tid & 1;     // A: 2 thr/row, 32 floats each
    const int brow = tid >> 2, bq = tid & 3;        // B: 4 thr/row, 16 bf16 each

    for (int t = 0; t < 32; t++) {
        __syncthreads();
        // A tile: 128 x 64 fp32 -> hi/lo bf16
        {
            const float4* src = (const float4*)(ap + (size_t)(row0 + arow) * SS + t * 64 + ahalf * 32);
            const uint32_t so = (uint32_t)arow * TSTRB + ahalf * 64;
            #pragma unroll
            for (int i = 0; i < 8; i++) {
                float4 f = src[i];
                uint32_t h0, l0, h1, l1;
                split2(f.x, f.y, h0, l0);
                split2(f.z, f.w, h1, l1);
                *(uint2*)(smem + OA_H + so + i * 8) = make_uint2(h0, h1);
                *(uint2*)(smem + OA_L + so + i * 8) = make_uint2(l0, l1);
            }
        }
        // B tile: 64 x 64 bf16 hi/lo
        {
            size_t o = (size_t)brow * SS + t * 64 + bq * 16;
            const uint4* sh = (const uint4*)(bhp + o);
            const uint4* sl = (const uint4*)(blp + o);
            const uint32_t so = (uint32_t)brow * TSTRB + bq * 32;
            #pragma unroll
            for (int i = 0; i < 2; i++) {
                *(uint4*)(smem + OB_H + so + i * 16) = sh[i];
                *(uint4*)(smem + OB_L + so + i * 16) = sl[i];
            }
        }
        __syncthreads();

        #pragma unroll
        for (int ks = 0; ks < 4; ks++) {
            const uint32_t kb = ks * 32;
            uint32_t a[2][4], bhf[2][4], blf[2][4];
            #pragma unroll
            for (int mf = 0; mf < 2; mf++) {
                uint32_t ad = sb + OA_H + (wm * 32 + mf * 16 + a_r) * TSTRB + kb + a_c;
                LDSM_X4(a[mf][0], a[mf][1], a[mf][2], a[mf][3], ad);
            }
            #pragma unroll
            for (int p = 0; p < 2; p++) {
                uint32_t bd = sb + OB_H + (wn * 32 + p * 16 + b_r) * TSTRB + kb + b_c;
                LDSM_X4(bhf[p][0], bhf[p][1], bhf[p][2], bhf[p][3], bd);
            }
            #pragma unroll
            for (int p = 0; p < 2; p++) {
                uint32_t bd = sb + OB_L + (wn * 32 + p * 16 + b_r) * TSTRB + kb + b_c;
                LDSM_X4(blf[p][0], blf[p][1], blf[p][2], blf[p][3], bd);
            }
            #pragma unroll
            for (int mf = 0; mf < 2; mf++)
                #pragma unroll
                for (int nf = 0; nf < 4; nf++) {
                    MMA_BF16(acc[mf][nf], a[mf][0], a[mf][1], a[mf][2], a[mf][3],
                             bhf[nf >> 1][(nf & 1) * 2], bhf[nf >> 1][(nf & 1) * 2 + 1]);
                    MMA_BF16(acc[mf][nf], a[mf][0], a[mf][1], a[mf][2], a[mf][3],
                             blf[nf >> 1][(nf & 1) * 2], blf[nf >> 1][(nf & 1) * 2 + 1]);
                }
            #pragma unroll
            for (int mf = 0; mf < 2; mf++) {
                uint32_t ad = sb + OA_L + (wm * 32 + mf * 16 + a_r) * TSTRB + kb + a_c;
                LDSM_X4(a[mf][0], a[mf][1], a[mf][2], a[mf][3], ad);
            }
            #pragma unroll
            for (int mf = 0; mf < 2; mf++)
                #pragma unroll
                for (int nf = 0; nf < 4; nf++)
                    MMA_BF16(acc[mf][nf], a[mf][0], a[mf][1], a[mf][2], a[mf][3],
                             bhf[nf >> 1][(nf & 1) * 2], bhf[nf >> 1][(nf & 1) * 2 + 1]);
        }
    }

    // epilogue: direct STG
    const int er = lane >> 2, ec = (lane & 3) * 2;
    #pragma unroll
    for (int mf = 0; mf < 2; mf++) {
        int r = row0 + wm * 32 + mf * 16 + er;
        #pragma unroll
        for (int nf = 0; nf < 4; nf++) {
            int c = wn * 32 + nf * 8 + ec;
            *(float2*)&ctx[(size_t)(b * SS + r) * EMBED + h * HD + c] =
                make_float2(acc[mf][nf][0], acc[mf][nf][1]);
            *(float2*)&ctx[(size_t)(b * SS + r + 8) * EMBED + h * HD + c] =
                make_float2(acc[mf][nf][2], acc[mf][nf][3]);
        }
    }
}

// ---------------------------------------------------------------------------
extern "C" void kernel_launch(void* const* d_in, const int* in_sizes, int n_in,
                              void* d_out, int out_size)
{
    const float* query = (const float*)d_in[0];
    const float* key   = (const float*)d_in[1];
    const float* value = (const float*)d_in[2];
    const float* Wq = (const float*)d_in[3];
    const float* bq = (const float*)d_in[4];
    const float* Wk = (const float*)d_in[5];
    const float* bk = (const float*)d_in[6];
    const float* Wv = (const float*)d_in[7];
    const float* bv = (const float*)d_in[8];
    const float* Wo = (const float*)d_in[9];
    const float* bo = (const float*)d_in[10];
    float* out = (float*)d_out;

    const size_t out_elems  = (size_t)MROWS * EMBED;
    const size_t attn_elems = (size_t)NBH * SS * SS;

    float *pq, *pk, *pv, *pctx, *pattn;
    __nv_bfloat16 *pqh, *pql, *pkh, *pkl, *pvth, *pvtl;
    cudaGetSymbolAddress((void**)&pq,    g_q);
    cudaGetSymbolAddress((void**)&pk,    g_k);
    cudaGetSymbolAddress((void**)&pv,    g_v);
    cudaGetSymbolAddress((void**)&pctx,  g_ctx);
    cudaGetSymbolAddress((void**)&pattn, g_attn);
    cudaGetSymbolAddress((void**)&pqh,   g_qh);
    cudaGetSymbolAddress((void**)&pql,   g_ql);
    cudaGetSymbolAddress((void**)&pkh,   g_kh);
    cudaGetSymbolAddress((void**)&pkl,   g_kl);
    cudaGetSymbolAddress((void**)&pvth,  g_vth);
    cudaGetSymbolAddress((void**)&pvtl,  g_vtl);

    float* attn = ((size_t)out_size >= out_elems + attn_elems) ? (out + out_elems) : pattn;

    cudaFuncSetAttribute(scores_mma, cudaFuncAttributeMaxDynamicSharedMemorySize, SC_SMEM);
    cudaFuncSetAttribute(context_mma, cudaFuncAttributeMaxDynamicSharedMemorySize, CTX_SMEM);

    dim3 gB(EMBED / 64, MROWS / 64);
    gemm_bias_kernel<<<gB, 256>>>(query, Wq, bq, pq, MROWS, EMBED, EMBED);
    gemm_bias_kernel<<<gB, 256>>>(key,   Wk, bk, pk, MROWS, EMBED, EMBED);
    gemm_bias_kernel<<<gB, 256>>>(value, Wv, bv, pv, MROWS, EMBED, EMBED);

    const int n4 = (MROWS * EMBED) / 4;
    split_hl_kernel<<<n4 / 256, 256>>>((const float4*)pq, (uint2*)pqh, (uint2*)pql, n4);
    split_hl_kernel<<<n4 / 256, 256>>>((const float4*)pk, (uint2*)pkh, (uint2*)pkl, n4);
    split_vT_kernel<<<dim3(SS / 32, HD / 32, NBH), dim3(32, 8)>>>(pv, pvth, pvtl);

    scores_mma<<<dim3(SS / 128, SS / 128, NBH), 256, SC_SMEM>>>(pqh, pql, pkh, pkl, attn);

    softmax_kernel<<<NBH * SS, 256>>>(attn);

    context_mma<<<dim3(SS / 128, NBH), 256, CTX_SMEM>>>(attn, pvth, pvtl, pctx);

    gemm_bias_kernel<<<gB, 256>>>(pctx, Wo, bo, out, MROWS, EMBED, EMBED);
}

// round 4
// speedup vs baseline: 1.9473x; 1.3236x over previous
#include <cuda_runtime.h>
#include <cuda_bf16.h>
#include <stdint.h>
#include <math.h>

#define EMBED 512
#define HEADS 8
#define HD 64
#define BB 4
#define SS 2048
#define MROWS (BB * SS) /* 8192 */
#define NBH (BB * HEADS) /* 32 */

// ------------------------- scratch (no allocs allowed) ----------------------
__device__ float g_v[(size_t)MROWS * EMBED];
__device__ float g_attn[(size_t)NBH * SS * SS];
__device__ __nv_bfloat16 g_tmph[(size_t)MROWS * EMBED];
__device__ __nv_bfloat16 g_tmpl[(size_t)MROWS * EMBED];
__device__ __nv_bfloat16 g_qh[(size_t)MROWS * EMBED];
__device__ __nv_bfloat16 g_ql[(size_t)MROWS * EMBED];
__device__ __nv_bfloat16 g_kh[(size_t)MROWS * EMBED];
__device__ __nv_bfloat16 g_kl[(size_t)MROWS * EMBED];
__device__ __nv_bfloat16 g_ctxh[(size_t)MROWS * EMBED];
__device__ __nv_bfloat16 g_ctxl[(size_t)MROWS * EMBED];
__device__ __nv_bfloat16 g_vth[(size_t)NBH * HD * SS];
__device__ __nv_bfloat16 g_vtl[(size_t)NBH * HD * SS];
__device__ __nv_bfloat16 g_wth[4 * EMBED * EMBED]; // Wt hi: q,k,v,o
__device__ __nv_bfloat16 g_wtl[4 * EMBED * EMBED]; // Wt lo

// ------------------------- helpers -----------------------------------------
__device__ __forceinline__ uint32_t smem_u32(const void* p) {
    uint32_t a;
    asm("{ .reg .u64 t; cvta.to.shared.u64 t, %1; cvt.u32.u64 %0, t; }" : "=r"(a) : "l"(p));
    return a;
}

#define LDSM_X4(r0, r1, r2, r3, a) \
    asm volatile("ldmatrix.sync.aligned.m8n8.x4.shared.b16 {%0,%1,%2,%3}, [%4];" \
                 : "=r"(r0), "=r"(r1), "=r"(r2), "=r"(r3) : "r"(a))

#define MMA_BF16(d, a0, a1, a2, a3, b0, b1) \
    asm volatile("mma.sync.aligned.m16n8k16.row.col.f32.bf16.bf16.f32 " \
                 "{%0,%1,%2,%3}, {%4,%5,%6,%7}, {%8,%9}, {%0,%1,%2,%3};" \
                 : "+f"((d)[0]), "+f"((d)[1]), "+f"((d)[2]), "+f"((d)[3]) \
                 : "r"(a0), "r"(a1), "r"(a2), "r"(a3), "r"(b0), "r"(b1))

__device__ __forceinline__ void split2(float a, float b, uint32_t& h, uint32_t& l) {
    __nv_bfloat16 ha = __float2bfloat16(a), hb = __float2bfloat16(b);
    float la = a - __bfloat162float(ha), lb = b - __bfloat162float(hb);
    __nv_bfloat16 lla = __float2bfloat16(la), llb = __float2bfloat16(lb);
    h = ((uint32_t)__bfloat16_as_ushort(hb) << 16) | (uint32_t)__bfloat16_as_ushort(ha);
    l = ((uint32_t)__bfloat16_as_ushort(llb) << 16) | (uint32_t)__bfloat16_as_ushort(lla);
}

// padded smem stride: 72 bf16 = 144 B (16B-aligned, ldmatrix conflict-free)
#define TSTR 72
#define TSTRB 144
#define TILE128B (128 * TSTRB) /* 18432 */
#define TILE64B  (64 * TSTRB)  /* 9216  */

// ---------------------------------------------------------------------------
// Weight transpose + split: Wt_h[n][k] = bf16hi(W[k][n]), Wt_l = lo.
// ---------------------------------------------------------------------------
__global__ __launch_bounds__(256) void split_wT_kernel(
    const float* __restrict__ W, __nv_bfloat16* __restrict__ th, __nv_bfloat16* __restrict__ tl)
{
    __shared__ float tile[32][33];
    const int n0 = blockIdx.x * 32, k0 = blockIdx.y * 32;
    const int tx = threadIdx.x, ty = threadIdx.y; // (32, 8)
    #pragma unroll
    for (int j = 0; j < 4; j++)
        tile[ty + j * 8][tx] = W[(size_t)(k0 + ty + j * 8) * EMBED + n0 + tx];
    __syncthreads();
    #pragma unroll
    for (int j = 0; j < 4; j++) {
        int nl = ty + j * 8;
        float f = tile[tx][nl]; // = W[k0+tx][n0+nl]
        __nv_bfloat16 hb = __float2bfloat16(f);
        __nv_bfloat16 lb = __float2bfloat16(f - __bfloat162float(hb));
        size_t o = (size_t)(n0 + nl) * EMBED + k0 + tx;
        th[o] = hb;
        tl[o] = lb;
    }
}

// ---------------------------------------------------------------------------
// Elementwise fp32 -> bf16 hi/lo split (for raw inputs)
// ---------------------------------------------------------------------------
__global__ __launch_bounds__(256) void split_hl_kernel(
    const float4* __restrict__ x, uint2* __restrict__ hi, uint2* __restrict__ lo, int n4)
{
    int i = blockIdx.x * 256 + threadIdx.x;
    if (i >= n4) return;
    float4 f = x[i];
    uint32_t h0, l0, h1, l1;
    split2(f.x, f.y, h0, l0);
    split2(f.z, f.w, h1, l1);
    hi[i] = make_uint2(h0, h1);
    lo[i] = make_uint2(l0, l1);
}

// ---------------------------------------------------------------------------
// V transpose + split: vT[bh][d][s] = split(v[b*S+s][h*64+d])
// ---------------------------------------------------------------------------
__global__ __launch_bounds__(256) void split_vT_kernel(
    const float* __restrict__ v, __nv_bfloat16* __restrict__ vth, __nv_bfloat16* __restrict__ vtl)
{
    __shared__ float tile[32][33];
    const int bh = blockIdx.z, b = bh >> 3, h = bh & 7;
    const int s0 = blockIdx.x * 32, d0 = blockIdx.y * 32;
    const int tx = threadIdx.x, ty = threadIdx.y; // (32, 8)
    #pragma unroll
    for (int j = 0; j < 4; j++) {
        int sl = ty + j * 8;
        tile[sl][tx] = v[(size_t)(b * SS + s0 + sl) * EMBED + h * HD + d0 + tx];
    }
    __syncthreads();
    #pragma unroll
    for (int j = 0; j < 4; j++) {
        int dl = ty + j * 8;
        float f = tile[tx][dl];
        __nv_bfloat16 hb = __float2bfloat16(f);
        __nv_bfloat16 lb = __float2bfloat16(f - __bfloat162float(hb));
        size_t o = ((size_t)bh * HD + d0 + dl) * SS + s0 + tx;
        vth[o] = hb;
        vtl[o] = lb;
    }
}

// ---------------------------------------------------------------------------
// Projection GEMM via mma.sync, split-bf16, K=512:
// C[m][n] = sum_k A[m][k] Wt[n][k] + bias[n]
// mode 0: write fp32 Cf.   mode 1: write bf16 hi/lo (Ch, Cl).
// Block 256 thr, tile 128x128, warps 2x4 (64x32 each), k chunks of 64.
// ---------------------------------------------------------------------------
#define PRJ_SMEM (4 * TILE128B) /* 73728 */
__global__ __launch_bounds__(256) void proj_mma(
    const __nv_bfloat16* __restrict__ ah, const __nv_bfloat16* __restrict__ al,
    const __nv_bfloat16* __restrict__ wth, const __nv_bfloat16* __restrict__ wtl,
    const float* __restrict__ bias,
    float* __restrict__ cf, __nv_bfloat16* __restrict__ ch, __nv_bfloat16* __restrict__ cl,
    int mode)
{
    extern __shared__ char smem[];
    const uint32_t sb = smem_u32(smem);
    const int tid = threadIdx.x, wid = tid >> 5, lane = tid & 31;
    const int row0 = blockIdx.y * 128, col0 = blockIdx.x * 128;
    const uint32_t OA_H = 0, OA_L = TILE128B, OB_H = 2 * TILE128B, OB_L = 3 * TILE128B;

    const int wm = wid >> 2, wn = wid & 3;
    float acc[4][4][4] = {};

    const uint32_t a_r = lane & 15, a_c = (lane >> 4) * 16;
    const uint32_t b_r = (lane & 7) + ((lane >> 4) & 1) * 8;
    const uint32_t b_c = ((lane >> 3) & 1) * 16;
    const int lrow = tid >> 1, lhalf = tid & 1;
    const uint32_t so = (uint32_t)lrow * TSTRB + lhalf * 64;

    for (int kc = 0; kc < EMBED; kc += 64) {
        __syncthreads();
        {
            size_t ao = (size_t)(row0 + lrow) * EMBED + kc + lhalf * 32;
            size_t bo = (size_t)(col0 + lrow) * EMBED + kc + lhalf * 32;
            const uint4* ahp = (const uint4*)(ah + ao);
            const uint4* alp = (const uint4*)(al + ao);
            const uint4* bhp = (const uint4*)(wth + bo);
            const uint4* blp = (const uint4*)(wtl + bo);
            #pragma unroll
            for (int i = 0; i < 4; i++) {
                *(uint4*)(smem + OA_H + so + i * 16) = ahp[i];
                *(uint4*)(smem + OA_L + so + i * 16) = alp[i];
                *(uint4*)(smem + OB_H + so + i * 16) = bhp[i];
                *(uint4*)(smem + OB_L + so + i * 16) = blp[i];
            }
        }
        __syncthreads();

        #pragma unroll
        for (int ks = 0; ks < 4; ks++) {
            const uint32_t kb = ks * 32;
            uint32_t a[4][4], bhf[2][4], blf[2][4];
            #pragma unroll
            for (int mf = 0; mf < 4; mf++) {
                uint32_t ad = sb + OA_H + (wm * 64 + mf * 16 + a_r) * TSTRB + kb + a_c;
                LDSM_X4(a[mf][0], a[mf][1], a[mf][2], a[mf][3], ad);
            }
            #pragma unroll
            for (int p = 0; p < 2; p++) {
                uint32_t bd = sb + OB_H + (wn * 32 + p * 16 + b_r) * TSTRB + kb + b_c;
                LDSM_X4(bhf[p][0], bhf[p][1], bhf[p][2], bhf[p][3], bd);
            }
            #pragma unroll
            for (int p = 0; p < 2; p++) {
                uint32_t bd = sb + OB_L + (wn * 32 + p * 16 + b_r) * TSTRB + kb + b_c;
                LDSM_X4(blf[p][0], blf[p][1], blf[p][2], blf[p][3], bd);
            }
            #pragma unroll
            for (int mf = 0; mf < 4; mf++)
                #pragma unroll
                for (int nf = 0; nf < 4; nf++) {
                    MMA_BF16(acc[mf][nf], a[mf][0], a[mf][1], a[mf][2], a[mf][3],
                             bhf[nf >> 1][(nf & 1) * 2], bhf[nf >> 1][(nf & 1) * 2 + 1]);
                    MMA_BF16(acc[mf][nf], a[mf][0], a[mf][1], a[mf][2], a[mf][3],
                             blf[nf >> 1][(nf & 1) * 2], blf[nf >> 1][(nf & 1) * 2 + 1]);
                }
            #pragma unroll
            for (int mf = 0; mf < 4; mf++) {
                uint32_t ad = sb + OA_L + (wm * 64 + mf * 16 + a_r) * TSTRB + kb + a_c;
                LDSM_X4(a[mf][0], a[mf][1], a[mf][2], a[mf][3], ad);
            }
            #pragma unroll
            for (int mf = 0; mf < 4; mf++)
                #pragma unroll
                for (int nf = 0; nf < 4; nf++)
                    MMA_BF16(acc[mf][nf], a[mf][0], a[mf][1], a[mf][2], a[mf][3],
                             bhf[nf >> 1][(nf & 1) * 2], bhf[nf >> 1][(nf & 1) * 2 + 1]);
        }
    }

    const int er = lane >> 2, ec = (lane & 3) * 2;
    #pragma unroll
    for (int mf = 0; mf < 4; mf++) {
        int r = row0 + wm * 64 + mf * 16 + er;
        #pragma unroll
        for (int nf = 0; nf < 4; nf++) {
            int c = col0 + wn * 32 + nf * 8 + ec;
            float b0 = bias[c], b1 = bias[c + 1];
            float v00 = acc[mf][nf][0] + b0, v01 = acc[mf][nf][1] + b1;
            float v10 = acc[mf][nf][2] + b0, v11 = acc[mf][nf][3] + b1;
            if (mode == 0) {
                *(float2*)&cf[(size_t)r * EMBED + c] = make_float2(v00, v01);
                *(float2*)&cf[(size_t)(r + 8) * EMBED + c] = make_float2(v10, v11);
            } else {
                uint32_t h0, l0, h1, l1;
                split2(v00, v01, h0, l0);
                split2(v10, v11, h1, l1);
                *(uint32_t*)&ch[(size_t)r * EMBED + c] = h0;
                *(uint32_t*)&cl[(size_t)r * EMBED + c] = l0;
                *(uint32_t*)&ch[(size_t)(r + 8) * EMBED + c] = h1;
                *(uint32_t*)&cl[(size_t)(r + 8) * EMBED + c] = l1;
            }
        }
    }
}

// ---------------------------------------------------------------------------
// Scores via mma.sync: S = (Q K^T) * 0.125, split-bf16. 128x128, K=64.
// ---------------------------------------------------------------------------
#define SC_SMEM (4 * TILE128B) /* 73728 */
__global__ __launch_bounds__(256) void scores_mma(
    const __nv_bfloat16* __restrict__ qh, const __nv_bfloat16* __restrict__ ql,
    const __nv_bfloat16* __restrict__ kh, const __nv_bfloat16* __restrict__ kl,
    float* __restrict__ attn)
{
    extern __shared__ char smem[];
    const uint32_t sb = smem_u32(smem);
    const int tid = threadIdx.x, wid = tid >> 5, lane = tid & 31;
    const int bh = blockIdx.z, b = bh >> 3, h = bh & 7;
    const int row0 = blockIdx.y * 128, col0 = blockIdx.x * 128;
    const uint32_t OA_H = 0, OA_L = TILE128B, OB_H = 2 * TILE128B, OB_L = 3 * TILE128B;

    {
        const int lrow = tid >> 1, lhalf = tid & 1;
        size_t qo = (size_t)(b * SS + row0 + lrow) * EMBED + h * HD + lhalf * 32;
        size_t ko = (size_t)(b * SS + col0 + lrow) * EMBED + h * HD + lhalf * 32;
        const uint4* qhp = (const uint4*)(qh + qo);
        const uint4* qlp = (const uint4*)(ql + qo);
        const uint4* khp = (const uint4*)(kh + ko);
        const uint4* klp = (const uint4*)(kl + ko);
        const uint32_t so = (uint32_t)lrow * TSTRB + lhalf * 64;
        #pragma unroll
        for (int i = 0; i < 4; i++) {
            *(uint4*)(smem + OA_H + so + i * 16) = qhp[i];
            *(uint4*)(smem + OA_L + so + i * 16) = qlp[i];
            *(uint4*)(smem + OB_H + so + i * 16) = khp[i];
            *(uint4*)(smem + OB_L + so + i * 16) = klp[i];
        }
    }
    __syncthreads();

    const int wm = wid >> 2, wn = wid & 3;
    float acc[4][4][4] = {};
    const uint32_t a_r = lane & 15, a_c = (lane >> 4) * 16;
    const uint32_t b_r = (lane & 7) + ((lane >> 4) & 1) * 8;
    const uint32_t b_c = ((lane >> 3) & 1) * 16;

    #pragma unroll
    for (int ks = 0; ks < 4; ks++) {
        const uint32_t kb = ks * 32;
        uint32_t a[4][4], bhf[2][4], blf[2][4];
        #pragma unroll
        for (int mf = 0; mf < 4; mf++) {
            uint32_t ad = sb + OA_H + (wm * 64 + mf * 16 + a_r) * TSTRB + kb + a_c;
            LDSM_X4(a[mf][0], a[mf][1], a[mf][2], a[mf][3], ad);
        }
        #pragma unroll
        for (int p = 0; p < 2; p++) {
            uint32_t bd = sb + OB_H + (wn * 32 + p * 16 + b_r) * TSTRB + kb + b_c;
            LDSM_X4(bhf[p][0], bhf[p][1], bhf[p][2], bhf[p][3], bd);
        }
        #pragma unroll
        for (int p = 0; p < 2; p++) {
            uint32_t bd = sb + OB_L + (wn * 32 + p * 16 + b_r) * TSTRB + kb + b_c;
            LDSM_X4(blf[p][0], blf[p][1], blf[p][2], blf[p][3], bd);
        }
        #pragma unroll
        for (int mf = 0; mf < 4; mf++)
            #pragma unroll
            for (int nf = 0; nf < 4; nf++) {
                MMA_BF16(acc[mf][nf], a[mf][0], a[mf][1], a[mf][2], a[mf][3],
                         bhf[nf >> 1][(nf & 1) * 2], bhf[nf >> 1][(nf & 1) * 2 + 1]);
                MMA_BF16(acc[mf][nf], a[mf][0], a[mf][1], a[mf][2], a[mf][3],
                         blf[nf >> 1][(nf & 1) * 2], blf[nf >> 1][(nf & 1) * 2 + 1]);
            }
        #pragma unroll
        for (int mf = 0; mf < 4; mf++) {
            uint32_t ad = sb + OA_L + (wm * 64 + mf * 16 + a_r) * TSTRB + kb + a_c;
            LDSM_X4(a[mf][0], a[mf][1], a[mf][2], a[mf][3], ad);
        }
        #pragma unroll
        for (int mf = 0; mf < 4; mf++)
            #pragma unroll
            for (int nf = 0; nf < 4; nf++)
                MMA_BF16(acc[mf][nf], a[mf][0], a[mf][1], a[mf][2], a[mf][3],
                         bhf[nf >> 1][(nf & 1) * 2], bhf[nf >> 1][(nf & 1) * 2 + 1]);
    }

    float* outp = attn + (size_t)bh * SS * SS;
    const int er = lane >> 2, ec = (lane & 3) * 2;
    #pragma unroll
    for (int mf = 0; mf < 4; mf++) {
        int r = row0 + wm * 64 + mf * 16 + er;
        #pragma unroll
        for (int nf = 0; nf < 4; nf++) {
            int c = col0 + wn * 32 + nf * 8 + ec;
            *(float2*)&outp[(size_t)r * SS + c] =
                make_float2(acc[mf][nf][0] * 0.125f, acc[mf][nf][1] * 0.125f);
            *(float2*)&outp[(size_t)(r + 8) * SS + c] =
                make_float2(acc[mf][nf][2] * 0.125f, acc[mf][nf][3] * 0.125f);
        }
    }
}

// ---------------------------------------------------------------------------
// Row softmax in place (rows of 2048)
// ---------------------------------------------------------------------------
__global__ __launch_bounds__(256) void softmax_kernel(float* __restrict__ attn)
{
    float* p = attn + (size_t)blockIdx.x * SS;
    const int tid = threadIdx.x;
    const int w = tid >> 5, l = tid & 31;
    __shared__ float smax[8];
    __shared__ float ssum[8];
    float v[8];
    #pragma unroll
    for (int j = 0; j < 8; j++) v[j] = p[tid + j * 256];
    float m = v[0];
    #pragma unroll
    for (int j = 1; j < 8; j++) m = fmaxf(m, v[j]);
    #pragma unroll
    for (int o = 16; o > 0; o >>= 1) m = fmaxf(m, __shfl_xor_sync(0xffffffffu, m, o));
    if (l == 0) smax[w] = m;
    __syncthreads();
    float bm = smax[0];
    #pragma unroll
    for (int i = 1; i < 8; i++) bm = fmaxf(bm, smax[i]);
    float s = 0.f;
    #pragma unroll
    for (int j = 0; j < 8; j++) { v[j] = __expf(v[j] - bm); s += v[j]; }
    #pragma unroll
    for (int o = 16; o > 0; o >>= 1) s += __shfl_xor_sync(0xffffffffu, s, o);
    if (l == 0) ssum[w] = s;
    __syncthreads();
    float bs = 0.f;
    #pragma unroll
    for (int i = 0; i < 8; i++) bs += ssum[i];
    const float inv = 1.0f / bs;
    #pragma unroll
    for (int j = 0; j < 8; j++) p[tid + j * 256] = v[j] * inv;
}

// ---------------------------------------------------------------------------
// Context via mma.sync: ctx[q][h*64+d] = sum_k attn[q][k] vT[d][k]
// Epilogue writes ctx as bf16 hi/lo (consumed directly by out-projection).
// ---------------------------------------------------------------------------
#define CTX_SMEM (2 * TILE128B + 2 * TILE64B) /* 55296 */
__global__ __launch_bounds__(256) void context_mma(
    const float* __restrict__ attn,
    const __nv_bfloat16* __restrict__ vth, const __nv_bfloat16* __restrict__ vtl,
    __nv_bfloat16* __restrict__ ctxh, __nv_bfloat16* __restrict__ ctxl)
{
    extern __shared__ char smem[];
    const uint32_t sb = smem_u32(smem);
    const int tid = threadIdx.x, wid = tid >> 5, lane = tid & 31;
    const int bh = blockIdx.y, b = bh >> 3, h = bh & 7;
    const int row0 = blockIdx.x * 128;
    const uint32_t OA_H = 0, OA_L = TILE128B, OB_H = 2 * TILE128B, OB_L = 2 * TILE128B + TILE64B;

    const float* ap = attn + (size_t)bh * SS * SS;
    const __nv_bfloat16* bhp = vth + (size_t)bh * HD * SS;
    const __nv_bfloat16* blp = vtl + (size_t)bh * HD * SS;

    const int wm = wid >> 1, wn = wid & 1;
    float acc[2][4][4] = {};

    const uint32_t a_r = lane & 15, a_c = (lane >> 4) * 16;
    const uint32_t b_r = (lane & 7) + ((lane >> 4) & 1) * 8;
    const uint32_t b_c = ((lane >> 3) & 1) * 16;

    const int arow = tid >> 1, ahalf = tid & 1;
    const int brow = tid >> 2, bq = tid & 3;

    for (int t = 0; t < 32; t++) {
        __syncthreads();
        {
            const float4* src = (const float4*)(ap + (size_t)(row0 + arow) * SS + t * 64 + ahalf * 32);
            const uint32_t so = (uint32_t)arow * TSTRB + ahalf * 64;
            #pragma unroll
            for (int i = 0; i < 8; i++) {
                float4 f = src[i];
                uint32_t h0, l0, h1, l1;
                split2(f.x, f.y, h0, l0);
                split2(f.z, f.w, h1, l1);
                *(uint2*)(smem + OA_H + so + i * 8) = make_uint2(h0, h1);
                *(uint2*)(smem + OA_L + so + i * 8) = make_uint2(l0, l1);
            }
        }
        {
            size_t o = (size_t)brow * SS + t * 64 + bq * 16;
            const uint4* sh = (const uint4*)(bhp + o);
            const uint4* sl = (const uint4*)(blp + o);
            const uint32_t so = (uint32_t)brow * TSTRB + bq * 32;
            #pragma unroll
            for (int i = 0; i < 2; i++) {
                *(uint4*)(smem + OB_H + so + i * 16) = sh[i];
                *(uint4*)(smem + OB_L + so + i * 16) = sl[i];
            }
        }
        __syncthreads();

        #pragma unroll
        for (int ks = 0; ks < 4; ks++) {
            const uint32_t kb = ks * 32;
            uint32_t a[2][4], bhf[2][4], blf[2][4];
            #pragma unroll
            for (int mf = 0; mf < 2; mf++) {
                uint32_t ad = sb + OA_H + (wm * 32 + mf * 16 + a_r) * TSTRB + kb + a_c;
                LDSM_X4(a[mf][0], a[mf][1], a[mf][2], a[mf][3], ad);
            }
            #pragma unroll
            for (int p = 0; p < 2; p++) {
                uint32_t bd = sb + OB_H + (wn * 32 + p * 16 + b_r) * TSTRB + kb + b_c;
                LDSM_X4(bhf[p][0], bhf[p][1], bhf[p][2], bhf[p][3], bd);
            }
            #pragma unroll
            for (int p = 0; p < 2; p++) {
                uint32_t bd = sb + OB_L + (wn * 32 + p * 16 + b_r) * TSTRB + kb + b_c;
                LDSM_X4(blf[p][0], blf[p][1], blf[p][2], blf[p][3], bd);
            }
            #pragma unroll
            for (int mf = 0; mf < 2; mf++)
                #pragma unroll
                for (int nf = 0; nf < 4; nf++) {
                    MMA_BF16(acc[mf][nf], a[mf][0], a[mf][1], a[mf][2], a[mf][3],
                             bhf[nf >> 1][(nf & 1) * 2], bhf[nf >> 1][(nf & 1) * 2 + 1]);
                    MMA_BF16(acc[mf][nf], a[mf][0], a[mf][1], a[mf][2], a[mf][3],
                             blf[nf >> 1][(nf & 1) * 2], blf[nf >> 1][(nf & 1) * 2 + 1]);
                }
            #pragma unroll
            for (int mf = 0; mf < 2; mf++) {
                uint32_t ad = sb + OA_L + (wm * 32 + mf * 16 + a_r) * TSTRB + kb + a_c;
                LDSM_X4(a[mf][0], a[mf][1], a[mf][2], a[mf][3], ad);
            }
            #pragma unroll
            for (int mf = 0; mf < 2; mf++)
                #pragma unroll
                for (int nf = 0; nf < 4; nf++)
                    MMA_BF16(acc[mf][nf], a[mf][0], a[mf][1], a[mf][2], a[mf][3],
                             bhf[nf >> 1][(nf & 1) * 2], bhf[nf >> 1][(nf & 1) * 2 + 1]);
        }
    }

    const int er = lane >> 2, ec = (lane & 3) * 2;
    #pragma unroll
    for (int mf = 0; mf < 2; mf++) {
        int r = row0 + wm * 32 + mf * 16 + er;
        #pragma unroll
        for (int nf = 0; nf < 4; nf++) {
            int c = wn * 32 + nf * 8 + ec;
            uint32_t h0, l0, h1, l1;
            split2(acc[mf][nf][0], acc[mf][nf][1], h0, l0);
            split2(acc[mf][nf][2], acc[mf][nf][3], h1, l1);
            size_t o0 = (size_t)(b * SS + r) * EMBED + h * HD + c;
            size_t o1 = (size_t)(b * SS + r + 8) * EMBED + h * HD + c;
            *(uint32_t*)&ctxh[o0] = h0;
            *(uint32_t*)&ctxl[o0] = l0;
            *(uint32_t*)&ctxh[o1] = h1;
            *(uint32_t*)&ctxl[o1] = l1;
        }
    }
}

// ---------------------------------------------------------------------------
extern "C" void kernel_launch(void* const* d_in, const int* in_sizes, int n_in,
                              void* d_out, int out_size)
{
    const float* query = (const float*)d_in[0];
    const float* key   = (const float*)d_in[1];
    const float* value = (const float*)d_in[2];
    const float* Wq = (const float*)d_in[3];
    const float* bq = (const float*)d_in[4];
    const float* Wk = (const float*)d_in[5];
    const float* bk = (const float*)d_in[6];
    const float* Wv = (const float*)d_in[7];
    const float* bv = (const float*)d_in[8];
    const float* Wo = (const float*)d_in[9];
    const float* bo = (const float*)d_in[10];
    float* out = (float*)d_out;

    const size_t out_elems  = (size_t)MROWS * EMBED;
    const size_t attn_elems = (size_t)NBH * SS * SS;
    const size_t wsz = (size_t)EMBED * EMBED;

    float *pv, *pattn;
    __nv_bfloat16 *ptmph, *ptmpl, *pqh, *pql, *pkh, *pkl, *pctxh, *pctxl, *pvth, *pvtl, *pwth, *pwtl;
    cudaGetSymbolAddress((void**)&pv,    g_v);
    cudaGetSymbolAddress((void**)&pattn, g_attn);
    cudaGetSymbolAddress((void**)&ptmph, g_tmph);
    cudaGetSymbolAddress((void**)&ptmpl, g_tmpl);
    cudaGetSymbolAddress((void**)&pqh,   g_qh);
    cudaGetSymbolAddress((void**)&pql,   g_ql);
    cudaGetSymbolAddress((void**)&pkh,   g_kh);
    cudaGetSymbolAddress((void**)&pkl,   g_kl);
    cudaGetSymbolAddress((void**)&pctxh, g_ctxh);
    cudaGetSymbolAddress((void**)&pctxl, g_ctxl);
    cudaGetSymbolAddress((void**)&pvth,  g_vth);
    cudaGetSymbolAddress((void**)&pvtl,  g_vtl);
    cudaGetSymbolAddress((void**)&pwth,  g_wth);
    cudaGetSymbolAddress((void**)&pwtl,  g_wtl);

    float* attn = ((size_t)out_size >= out_elems + attn_elems) ? (out + out_elems) : pattn;

    cudaFuncSetAttribute(proj_mma, cudaFuncAttributeMaxDynamicSharedMemorySize, PRJ_SMEM);
    cudaFuncSetAttribute(scores_mma, cudaFuncAttributeMaxDynamicSharedMemorySize, SC_SMEM);
    cudaFuncSetAttribute(context_mma, cudaFuncAttributeMaxDynamicSharedMemorySize, CTX_SMEM);

    // weight transpose + split
    dim3 gW(EMBED / 32, EMBED / 32);
    split_wT_kernel<<<gW, dim3(32, 8)>>>(Wq, pwth + 0 * wsz, pwtl + 0 * wsz);
    split_wT_kernel<<<gW, dim3(32, 8)>>>(Wk, pwth + 1 * wsz, pwtl + 1 * wsz);
    split_wT_kernel<<<gW, dim3(32, 8)>>>(Wv, pwth + 2 * wsz, pwtl + 2 * wsz);
    split_wT_kernel<<<gW, dim3(32, 8)>>>(Wo, pwth + 3 * wsz, pwtl + 3 * wsz);

    const int n4 = (MROWS * EMBED) / 4;
    dim3 gP(EMBED / 128, MROWS / 128); // (4, 64)

    // Q projection -> bf16 hi/lo
    split_hl_kernel<<<n4 / 256, 256>>>((const float4*)query, (uint2*)ptmph, (uint2*)ptmpl, n4);
    proj_mma<<<gP, 256, PRJ_SMEM>>>(ptmph, ptmpl, pwth + 0 * wsz, pwtl + 0 * wsz, bq,
                                    nullptr, pqh, pql, 1);
    // K projection -> bf16 hi/lo
    split_hl_kernel<<<n4 / 256, 256>>>((const float4*)key, (uint2*)ptmph, (uint2*)ptmpl, n4);
    proj_mma<<<gP, 256, PRJ_SMEM>>>(ptmph, ptmpl, pwth + 1 * wsz, pwtl + 1 * wsz, bk,
                                    nullptr, pkh, pkl, 1);
    // V projection -> fp32 (then transpose+split)
    split_hl_kernel<<<n4 / 256, 256>>>((const float4*)value, (uint2*)ptmph, (uint2*)ptmpl, n4);
    proj_mma<<<gP, 256, PRJ_SMEM>>>(ptmph, ptmpl, pwth + 2 * wsz, pwtl + 2 * wsz, bv,
                                    pv, nullptr, nullptr, 0);
    split_vT_kernel<<<dim3(SS / 32, HD / 32, NBH), dim3(32, 8)>>>(pv, pvth, pvtl);

    scores_mma<<<dim3(SS / 128, SS / 128, NBH), 256, SC_SMEM>>>(pqh, pql, pkh, pkl, attn);

    softmax_kernel<<<NBH * SS, 256>>>(attn);

    context_mma<<<dim3(SS / 128, NBH), 256, CTX_SMEM>>>(attn, pvth, pvtl, pctxh, pctxl);

    // output projection
    proj_mma<<<gP, 256, PRJ_SMEM>>>(pctxh, pctxl, pwth + 3 * wsz, pwtl + 3 * wsz, bo,
                                    out, nullptr, nullptr, 0);
}